// round 8
// baseline (speedup 1.0000x reference)
#include <cuda_runtime.h>
#include <cstdint>

#define K_DIM   2048
#define N_EXP   64
#define TM      128
#define TK      64
#define NKT     32
#define THREADS 512
#define ASTRIDE 72
#define ASTAGE  (TM * ASTRIDE)      // floats per A stage (9216)
#define BWORDS  4096                // uint32 per B stage (16KB)
#define LDL     72
#define TOPK_TEMP 2.0f
#define SMEM_BYTES (3 * ASTAGE * 4 + 4 * BWORDS * 4)   // 110592 + 65536 = 176128

__device__ uint32_t g_wfrag[NKT * BWORDS];

__device__ __forceinline__ uint32_t pack2(float f0, float f1) {
    uint32_t r;
    asm("cvt.rn.bf16x2.f32 %0, %1, %2;" : "=r"(r) : "f"(f1), "f"(f0));
    return r;
}
__device__ __forceinline__ void split2(float f0, float f1, uint32_t &h, uint32_t &l) {
    h = pack2(f0, f1);
    float h0 = __uint_as_float(h << 16);
    float h1 = __uint_as_float(h & 0xFFFF0000u);
    l = pack2(f0 - h0, f1 - h1);
}
__device__ __forceinline__ void mma16816(float *d,
                                         uint32_t a0, uint32_t a1, uint32_t a2, uint32_t a3,
                                         uint32_t b0, uint32_t b1) {
    asm volatile("mma.sync.aligned.m16n8k16.row.col.f32.bf16.bf16.f32 "
                 "{%0,%1,%2,%3}, {%4,%5,%6,%7}, {%8,%9}, {%0,%1,%2,%3};"
                 : "+f"(d[0]), "+f"(d[1]), "+f"(d[2]), "+f"(d[3])
                 : "r"(a0), "r"(a1), "r"(a2), "r"(a3), "r"(b0), "r"(b1));
}
__device__ __forceinline__ void cp16(uint32_t dst, const void* src) {
    asm volatile("cp.async.cg.shared.global [%0], [%1], 16;" :: "r"(dst), "l"(src));
}

__global__ __launch_bounds__(256)
void dhr_wprep_kernel(const float* __restrict__ w)
{
    const int kt = blockIdx.x;
    const int t  = threadIdx.x;
    const int bp  = t & 31;
    const int bks = bp >> 3;
    const int brg = (bp >> 2) & 1;
    const int bn0 = t >> 5;
    const int bln = (bn0 << 2) | (bp & 3);
    const float* pW = w + bn0 * K_DIM + kt * TK + 2 * bp;
    uint32_t* dst0 = g_wfrag + kt * BWORDS;
    #pragma unroll
    for (int i = 0; i < 8; i++) {
        float2 wv = *(const float2*)(pW + i * 8 * K_DIM);
        uint32_t h, l; split2(wv.x, wv.y, h, l);
        uint32_t* d = dst0 + (((bks * 8 + i) * 32 + bln) << 2);
        d[brg] = h; d[2 + brg] = l;
    }
}

__global__ __launch_bounds__(THREADS, 1)
void dhr_pipe_kernel(const float* __restrict__ x,
                     const float* __restrict__ bias,
                     const int*   __restrict__ mat,
                     float* __restrict__ out)
{
    extern __shared__ __align__(16) float smem[];
    uint32_t* Bbase = (uint32_t*)(smem + 3 * ASTAGE);

    const int t    = threadIdx.x;
    const int wid  = t >> 5;
    const int lane = t & 31;
    const int q    = lane & 3;
    const int g    = lane >> 2;
    const int kh     = wid & 1;
    const int stripe = (wid >> 1) & 3;
    const int nH     = wid >> 3;
    const int mrow   = stripe * 32;
    const long rowBase = (long)blockIdx.x * TM;

    const uint32_t aSmem = (uint32_t)__cvta_generic_to_shared(smem);
    const uint32_t bSmem = (uint32_t)__cvta_generic_to_shared(Bbase);

    float acc[2][4][4];
    #pragma unroll
    for (int m = 0; m < 2; m++)
        #pragma unroll
        for (int j = 0; j < 4; j++)
            acc[m][j][0] = acc[m][j][1] = acc[m][j][2] = acc[m][j][3] = 0.f;

    // cross-iteration A fragments: [kk][m][reg]
    uint32_t fah[2][2][4], fal[2][2][4];

    // ---- prologue: stages 0,1 ----
    #pragma unroll
    for (int s0 = 0; s0 < 2; s0++) {
        #pragma unroll
        for (int ss = 0; ss < 4; ss++) {
            int idx = ss * THREADS + t;
            int r = idx >> 4, cc = idx & 15;
            cp16(aSmem + (s0 * ASTAGE + r * ASTRIDE) * 4 + cc * 16,
                 x + (rowBase + r) * K_DIM + s0 * TK + cc * 4);
        }
        #pragma unroll
        for (int ss = 0; ss < 2; ss++) {
            int idx = ss * THREADS + t;
            cp16(bSmem + s0 * BWORDS * 4 + idx * 16,
                 g_wfrag + s0 * BWORDS + idx * 4);
        }
        asm volatile("cp.async.commit_group;");
    }

    // ---- pipelined mainloop: iter kt loads tile kt, MMAs tile kt-1 ----
    for (int kt = 0; kt <= NKT; kt++) {
        if (kt < NKT) {
            asm volatile("cp.async.wait_group %0;" :: "n"(1));
            __syncthreads();
            if (kt + 2 < NKT) {
                int sa = (kt + 2) % 3;
                int sbg = (kt + 2) & 3;
                #pragma unroll
                for (int ss = 0; ss < 4; ss++) {
                    int idx = ss * THREADS + t;
                    int r = idx >> 4, cc = idx & 15;
                    cp16(aSmem + (sa * ASTAGE + r * ASTRIDE) * 4 + cc * 16,
                         x + (rowBase + r) * K_DIM + (kt + 2) * TK + cc * 4);
                }
                #pragma unroll
                for (int ss = 0; ss < 2; ss++) {
                    int idx = ss * THREADS + t;
                    cp16(bSmem + sbg * BWORDS * 4 + idx * 16,
                         g_wfrag + (kt + 2) * BWORDS + idx * 4);
                }
            }
            asm volatile("cp.async.commit_group;");
        }

        const float*    As = smem + (kt % 3) * ASTAGE;           // tile kt
        const uint32_t* Bs = Bbase + ((kt + 3) & 3) * BWORDS;    // tile kt-1

        #pragma unroll
        for (int kk = 0; kk < 2; kk++) {
            const int ks = kh * 2 + kk;

            // B operands of tile kt-1 (register-resident before MMAs)
            uint4 bq[4];
            if (kt > 0) {
                #pragma unroll
                for (int j = 0; j < 4; j++)
                    bq[j] = *(const uint4*)(Bs + (((ks * 8 + nH * 4 + j) * 32 + lane) << 2));
            }

            // A loads of tile kt (independent of MMAs below)
            float2 av[8];
            if (kt < NKT) {
                const float* p = As + (mrow + g) * ASTRIDE + ks * 16 + 2 * q;
                #pragma unroll
                for (int m = 0; m < 2; m++) {
                    const float* pm = p + m * 16 * ASTRIDE;
                    av[m * 4 + 0] = *(const float2*)(pm);
                    av[m * 4 + 1] = *(const float2*)(pm + 8 * ASTRIDE);
                    av[m * 4 + 2] = *(const float2*)(pm + 8);
                    av[m * 4 + 3] = *(const float2*)(pm + 8 * ASTRIDE + 8);
                }
            }

            // MMAs for tile kt-1: term-major -> same-acc spacing of 8
            if (kt > 0) {
                #pragma unroll
                for (int m = 0; m < 2; m++)
                    #pragma unroll
                    for (int j = 0; j < 4; j++)
                        mma16816(acc[m][j], fah[kk][m][0], fah[kk][m][1],
                                 fah[kk][m][2], fah[kk][m][3], bq[j].x, bq[j].y);
                #pragma unroll
                for (int m = 0; m < 2; m++)
                    #pragma unroll
                    for (int j = 0; j < 4; j++)
                        mma16816(acc[m][j], fah[kk][m][0], fah[kk][m][1],
                                 fah[kk][m][2], fah[kk][m][3], bq[j].z, bq[j].w);
                #pragma unroll
                for (int m = 0; m < 2; m++)
                    #pragma unroll
                    for (int j = 0; j < 4; j++)
                        mma16816(acc[m][j], fal[kk][m][0], fal[kk][m][1],
                                 fal[kk][m][2], fal[kk][m][3], bq[j].x, bq[j].y);
            }

            // convert tile kt's fragments (overlaps MMAs above in the scheduler)
            if (kt < NKT) {
                #pragma unroll
                for (int m = 0; m < 2; m++)
                    #pragma unroll
                    for (int r = 0; r < 4; r++)
                        split2(av[m * 4 + r].x, av[m * 4 + r].y,
                               fah[kk][m][r], fal[kk][m][r]);
            }
        }
    }
    __syncthreads();

    // ---- epilogue: combine K-split partials + bias into SMEM logits ----
    float* L = smem;
    if (kh == 0) {
        #pragma unroll
        for (int m = 0; m < 2; m++) {
            #pragma unroll
            for (int j = 0; j < 4; j++) {
                int c = (nH * 4 + j) * 8 + 2 * q;
                float b0 = __ldg(&bias[c]);
                float b1 = __ldg(&bias[c + 1]);
                int r0 = mrow + g + 16 * m;
                L[r0 * LDL + c]           = acc[m][j][0] + b0;
                L[r0 * LDL + c + 1]       = acc[m][j][1] + b1;
                L[(r0 + 8) * LDL + c]     = acc[m][j][2] + b0;
                L[(r0 + 8) * LDL + c + 1] = acc[m][j][3] + b1;
            }
        }
    }
    __syncthreads();
    if (kh == 1) {
        #pragma unroll
        for (int m = 0; m < 2; m++) {
            #pragma unroll
            for (int j = 0; j < 4; j++) {
                int c = (nH * 4 + j) * 8 + 2 * q;
                int r0 = mrow + g + 16 * m;
                L[r0 * LDL + c]           += acc[m][j][0];
                L[r0 * LDL + c + 1]       += acc[m][j][1];
                L[(r0 + 8) * LDL + c]     += acc[m][j][2];
                L[(r0 + 8) * LDL + c + 1] += acc[m][j][3];
            }
        }
    }
    __syncthreads();

    // ---- routing ----
    if (t < TM) {
        bool any_immature = false;
        #pragma unroll 8
        for (int e = 0; e < N_EXP; e++)
            any_immature |= (__ldg(&mat[e]) == 0);

        float* row = &L[t * LDL];
        if (!any_immature) {
            float v1 = -__int_as_float(0x7f800000), v2 = v1;
            int i1 = 0, i2 = 0;
            #pragma unroll 8
            for (int e = 0; e < N_EXP; e++) {
                float v = row[e];
                if (v > v1)      { v2 = v1; i2 = i1; v1 = v; i1 = e; }
                else if (v > v2) { v2 = v;  i2 = e; }
            }
            float e2  = __expf(v2 - v1);
            float inv = 1.0f / (1.0f + e2);
            #pragma unroll 8
            for (int e = 0; e < N_EXP; e++) row[e] = 0.0f;
            row[i1] = inv;
            row[i2] = e2 * inv;
        } else {
            float m = -__int_as_float(0x7f800000);
            #pragma unroll 8
            for (int e = 0; e < N_EXP; e++) m = fmaxf(m, row[e]);
            float s = 0.0f;
            float tmp[N_EXP];
            #pragma unroll 8
            for (int e = 0; e < N_EXP; e++) {
                float v = __expf((row[e] - m) * (1.0f / TOPK_TEMP));
                tmp[e] = v; s += v;
            }
            float invs = 1.0f / s;
            #pragma unroll 8
            for (int e = 0; e < N_EXP; e++) row[e] = tmp[e] * invs;
        }
    }
    __syncthreads();

    // ---- coalesced float4 store of 128x64 tile ----
    #pragma unroll
    for (int s = 0; s < (TM * N_EXP / 4) / THREADS; s++) {   // 4
        int idx = s * THREADS + t;
        int r = idx >> 4;
        int c = (idx & 15) << 2;
        float4 v = *(const float4*)&L[r * LDL + c];
        *(float4*)(out + (rowBase + r) * N_EXP + c) = v;
    }
}

extern "C" void kernel_launch(void* const* d_in, const int* in_sizes, int n_in,
                              void* d_out, int out_size)
{
    const float* x   = (const float*)d_in[0];   // [16384, 2048]
    const float* w   = (const float*)d_in[1];   // [64, 2048]
    const float* b   = (const float*)d_in[2];   // [64]
    const int*   mat = (const int*)  d_in[3];   // [64]
    float* out = (float*)d_out;                 // [16384, 64]

    cudaFuncSetAttribute(dhr_pipe_kernel,
                         cudaFuncAttributeMaxDynamicSharedMemorySize, SMEM_BYTES);

    dhr_wprep_kernel<<<NKT, 256>>>(w);

    int rows = in_sizes[0] / K_DIM;             // 16384
    int grid = rows / TM;                       // 128
    dhr_pipe_kernel<<<grid, THREADS, SMEM_BYTES>>>(x, b, mat, out);
}